// round 15
// baseline (speedup 1.0000x reference)
#include <cuda_runtime.h>
#include <cuda_fp16.h>
#include <math.h>
#include <stdint.h>

#define BB 65536
#define D 128
#define NH 4
#define DH 32
#define DMLP 512
#define DMEM 64
#define NP 150
#define EQTOK 151
#define NOUT 150
#define NPAD 160

// ---------------- warp-level fp16 tensor-core mma (fp32 accumulate) ----------------
__device__ __forceinline__ void mma16816(float* c, const uint32_t* a, const uint32_t* b){
    asm volatile(
        "mma.sync.aligned.m16n8k16.row.col.f32.f16.f16.f32 "
        "{%0,%1,%2,%3}, {%4,%5,%6,%7}, {%8,%9}, {%0,%1,%2,%3};"
        : "+f"(c[0]), "+f"(c[1]), "+f"(c[2]), "+f"(c[3])
        : "r"(a[0]), "r"(a[1]), "r"(a[2]), "r"(a[3]), "r"(b[0]), "r"(b[1]));
}
__device__ __forceinline__ void ldsm4(uint32_t* r, uint32_t addr){
    asm volatile("ldmatrix.sync.aligned.m8n8.x4.shared.b16 {%0,%1,%2,%3}, [%4];"
        : "=r"(r[0]), "=r"(r[1]), "=r"(r[2]), "=r"(r[3]) : "r"(addr));
}
__device__ __forceinline__ uint32_t smem_u32(const void* p){
    uint32_t a;
    asm("{ .reg .u64 t; cvta.to.shared.u64 t, %1; cvt.u32.u64 %0, t; }" : "=r"(a) : "l"(p));
    return a;
}
__device__ __forceinline__ void cpa16(uint32_t dst, const void* src){
    asm volatile("cp.async.cg.shared.global [%0], [%1], 16;" :: "r"(dst), "l"(src) : "memory");
}
#define CP_COMMIT() asm volatile("cp.async.commit_group;" ::: "memory")
#define CP_WAIT1()  asm volatile("cp.async.wait_group 1;" ::: "memory")
#define CP_WAIT0()  asm volatile("cp.async.wait_group 0;" ::: "memory")

// ---------------- persistent scratch ----------------
__device__ float g_X3F[NP*D];
__device__ float g_Q3[NP*D];
__device__ float g_V0[NP*D];
__device__ float g_V3[NP*D];
__device__ float g_VM[NP*D];
__device__ float g_S0[NP*NH];
__device__ float g_S3[NP*NH];
__device__ float g_SM[NP*NH];
__device__ float g_K1T[NP*D];
__device__ float g_V1T[NP*D];
__device__ float g_K2T[NP*D];
__device__ float g_V2T[NP*D];
__device__ float g_T1[NP*NP*NH];
__device__ float g_T2[NP*NP*NH];
__device__ float g_biasC[NPAD];       // b_un padded
// weight images (fp16, swizzled, B-operand layout: row=output col, col=k)
__device__ uint4 g_WOimg[2048];
__device__ uint4 g_W1img[4*2048];
__device__ uint4 g_W2img[4*2048];     // W2 slabs: rows n(128 model dims), k within slab
__device__ uint4 g_WUimg[2560];       // Wun image: rows n(160 padded), k=128

// image addressing: rows of 256B (128 fp16), 16B chunks XOR-swizzled by (row&7)
__device__ __forceinline__ unsigned img_off_elem(int r, int k){
    return (unsigned)r*256u + ((((unsigned)k>>3)^((unsigned)r&7u))*16u) + ((unsigned)k&7u)*2u;
}
// f32 pair -> fp16, 4-byte write at (r, col even)
__device__ __forceinline__ void wpair(char* img, int r, int col, float a, float b){
    __half h0=__float2half(a), h1=__float2half(b);
    unsigned off = (unsigned)r*256u + ((((unsigned)col>>3)^((unsigned)r&7u))*16u) + ((unsigned)col&7u)*2u;
    unsigned hv = (unsigned)*(unsigned short*)&h0 | ((unsigned)*(unsigned short*)&h1<<16);
    *(unsigned*)(img+off)=hv;
}
// read fp16 pair at (r, col even)
__device__ __forceinline__ float2 rpair(const char* img, int r, int col){
    unsigned off = (unsigned)r*256u + ((((unsigned)col>>3)^((unsigned)r&7u))*16u) + ((unsigned)col&7u)*2u;
    __half2 h = *(const __half2*)(img+off);
    return __half22float2(h);
}

// ---------------- precompute per-p and per-token tables ----------------
__global__ void k_precompute(
    const float* __restrict__ emb, const float* __restrict__ pos,
    const float* __restrict__ W_mem, const float* __restrict__ b_mem,
    const float* __restrict__ W_sur, const float* __restrict__ b_sur,
    const float* __restrict__ W_m2r, const float* __restrict__ b_m2r,
    const float* __restrict__ W_Q, const float* __restrict__ W_K,
    const float* __restrict__ W_V)
{
    int p = blockIdx.x;
    int d = threadIdx.x; // 128 threads
    __shared__ float x0f[D], zz[DMEM], diffs[D], zu[DMEM], memv[D];
    __shared__ float x0full[D], x3full[D];
    __shared__ float sq[D], sk0[D], sk3[D], skm[D], e1v[D], e2v[D];

    x0f[d] = emb[p*D+d] + pos[d];
    __syncthreads();
    if (d < DMEM){
        float acc = b_mem[d];
        for (int e=0;e<D;e++) acc += x0f[e]*W_mem[e*DMEM+d];
        zz[d] = acc/(1.f+expf(-acc));        // silu
    }
    __syncthreads();
    {
        float pr = b_sur[d];
        for (int j=0;j<DMEM;j++) pr += zz[j]*W_sur[j*D+d];
        diffs[d] = x0f[d] - pr;
    }
    __syncthreads();
    if (d < DMEM){
        float acc = 0.f;
        for (int e=0;e<D;e++) acc += diffs[e]*W_mem[e*DMEM+d];
        zu[d] = zz[d] + acc/(1.f+expf(-acc));
    }
    __syncthreads();
    {
        float mm = b_m2r[d];
        for (int j=0;j<DMEM;j++) mm += zu[j]*W_m2r[j*D+d];
        memv[d]  = mm;
        x0full[d] = x0f[d] + mm;
        x3full[d] = emb[EQTOK*D+d] + pos[3*D+d] + mm;
        e1v[d] = emb[p*D+d] + pos[D+d];
        e2v[d] = emb[p*D+d] + pos[2*D+d];
    }
    __syncthreads();

    int h = d>>5;
    const float* Wq = W_Q + h*D*DH + (d&31);
    const float* Wk = W_K + h*D*DH + (d&31);
    const float* Wv = W_V + h*D*DH + (d&31);
    float q=0,k0=0,k3=0,km=0,v0=0,v3=0,vm=0,k1=0,v1=0,k2=0,v2=0;
    for (int e=0;e<D;e++){
        float wq=Wq[e*DH], wk=Wk[e*DH], wv=Wv[e*DH];
        q  += x3full[e]*wq;
        k0 += x0full[e]*wk; k3 += x3full[e]*wk; km += memv[e]*wk;
        v0 += x0full[e]*wv; v3 += x3full[e]*wv; vm += memv[e]*wv;
        k1 += e1v[e]*wk;    v1 += e1v[e]*wv;
        k2 += e2v[e]*wk;    v2 += e2v[e]*wv;
    }
    q *= 0.17677669529663687f;  // 1/sqrt(32)
    g_Q3[p*D+d]=q;  g_X3F[p*D+d]=x3full[d];
    g_V0[p*D+d]=v0; g_V3[p*D+d]=v3; g_VM[p*D+d]=vm;
    g_K1T[p*D+d]=k1; g_V1T[p*D+d]=v1; g_K2T[p*D+d]=k2; g_V2T[p*D+d]=v2;
    sq[d]=q; sk0[d]=k0; sk3[d]=k3; skm[d]=km;
    __syncthreads();
    if (d < 3*NH){
        int hh = d & 3, which = d >> 2;
        const float* kk = (which==0) ? sk0 : (which==1 ? sk3 : skm);
        float acc=0.f;
        for (int t=0;t<DH;t++) acc += sq[hh*DH+t]*kk[hh*DH+t];
        float* dst = (which==0) ? g_S0 : (which==1 ? g_S3 : g_SM);
        dst[p*NH+hh] = acc;
    }
}

// ---------------- bilinear score tables T1/T2 ----------------
__global__ void k_ttab(){
    int p = blockIdx.x;
    __shared__ float q[D];
    int t = threadIdx.x;
    q[t] = g_Q3[p*D+t];
    __syncthreads();
    for (int a=t; a<NP; a+=128){
        for (int h=0;h<NH;h++){
            float s1=0.f, s2=0.f;
            for (int k=0;k<DH;k++){
                float qv = q[h*DH+k];
                s1 += qv*g_K1T[a*D+h*DH+k];
                s2 += qv*g_K2T[a*D+h*DH+k];
            }
            g_T1[(p*NP+a)*NH+h] = s1;
            g_T2[(p*NP+a)*NH+h] = s2;
        }
    }
}

// ---------------- merged weight-image prep: WO, W1, W2, Wun, biasC ----------------
__global__ void k_wprep(const float* __restrict__ WO, const float* __restrict__ W1,
                        const float* __restrict__ W2, const float* __restrict__ Wun,
                        const float* __restrict__ b_un){
    int bx = blockIdx.x;     // 0..1311
    int k  = threadIdx.x;    // 0..127
    float val; char* img; int rowc;
    if (bx < 128){
        rowc = bx;
        val = WO[k*D + rowc];
        img = (char*)g_WOimg;
    } else if (bx < 640){
        int idx = bx - 128;
        int ch = idx >> 7, j = idx & 127;
        rowc = j;
        val = W1[k*DMLP + ch*128 + j];
        img = (char*)g_W1img + (size_t)ch*32768;
    } else if (bx < 1152){
        int idx = bx - 640;
        int ch = idx >> 7, n = idx & 127;
        rowc = n;
        val = W2[(ch*128 + k)*D + n];
        img = (char*)g_W2img + (size_t)ch*32768;
    } else {
        int n = bx - 1152;   // 0..159
        rowc = n;
        val = (n < NOUT) ? Wun[k*NOUT + n] : 0.f;
        img = (char*)g_WUimg;
        if (k == 0) g_biasC[n] = (n < NOUT) ? b_un[n] : 0.f;
    }
    __half h = __float2half(val);
    unsigned off = img_off_elem(rowc, k);
    *(unsigned short*)(img + off) = *(unsigned short*)&h;
}

// ---------------- single-M-tile MMA pass via ldmatrix (fp32 accumulate) ----------------
template<int NT>
__device__ __forceinline__ void mma_pass1(float (&acc)[NT][4], uint32_t Aimg, uint32_t Bimg,
                                          int rowbase, int colbase, int lane){
    int q = lane >> 3, j = lane & 7;
    unsigned rA = (unsigned)(rowbase + ((q&1)<<3) + j);
    unsigned rA7 = rA & 7u, chselA = (unsigned)(q>>1);
    unsigned baseA = Aimg + rA*256u;
    unsigned rB = (unsigned)(colbase + ((q>>1)<<3) + j);
    unsigned rB7 = rB & 7u, chselB = (unsigned)(q&1);
    unsigned baseB = Bimg + rB*256u;
    #pragma unroll
    for (int ks=0; ks<8; ks++){
        unsigned offA = ((((unsigned)ks*2u + chselA) ^ rA7) << 4);
        uint32_t afr[4];
        ldsm4(afr, baseA + offA);
        unsigned offB = ((((unsigned)ks*2u + chselB) ^ rB7) << 4);
        uint32_t bfr[NT][2];
        #pragma unroll
        for (int c=0; c<NT/2; c++){
            uint32_t t[4];
            ldsm4(t, baseB + (unsigned)c*4096u + offB);
            bfr[2*c][0]=t[0]; bfr[2*c][1]=t[1]; bfr[2*c+1][0]=t[2]; bfr[2*c+1][1]=t[3];
        }
        #pragma unroll
        for (int nt=0; nt<NT; nt++) mma16816(acc[nt], afr, bfr[nt]);
    }
}

// ---------------- fused: attention -> GEMM chain, M=64 per CTA, 2 CTAs/SM ----------------
#define OFF_X3  16384
#define OFF_WB0 32768
#define OFF_WB1 65536
#define FU_SMEM (65536+40960)

__global__ void __launch_bounds__(256,2)
k_fused(const int* __restrict__ pv, const int* __restrict__ av, const int* __restrict__ bv,
        const float* __restrict__ bias1, const float* __restrict__ b2, float* __restrict__ out){
    extern __shared__ char sm[];
    char* B1  = sm;                // 16KB: attn image, later H-chunk / y images (64 rows)
    char* X3  = sm + OFF_X3;       // 16KB: x3 image (64 rows)
    char* WB0 = sm + OFF_WB0;      // 32KB weight buffer 0 (WO, W2 slabs)
    char* WB1 = sm + OFF_WB1;      // 40KB weight buffer 1 (W1 slabs, Wun)
    __shared__ int ps[64];
    __shared__ float sb1[128];
    __shared__ float sb2[128];
    __shared__ float sbc[NPAD];

    uint32_t b1A = smem_u32(B1), x3A = smem_u32(X3), w0A = smem_u32(WB0), w1A = smem_u32(WB1);

    int tid = threadIdx.x, wid = tid>>5, lane = tid&31;
    int blk = blockIdx.x;          // 0..1023, 64 rows each
    int R0  = blk*64;
    int wm = wid & 3, wn = wid >> 2;       // 4 M-groups x 2 N-groups
    int lr = lane >> 2, lq = lane & 3;
    int rowbase = wm*16;

    // g0: WO -> WB0   (issued before the attention compute so it overlaps)
    for (int i=tid;i<2048;i+=256) cpa16(w0A + i*16u, g_WOimg + i);
    CP_COMMIT();
    // g1: W1_0 -> WB1
    for (int i=tid;i<2048;i+=256) cpa16(w1A + i*16u, g_W1img + i);
    CP_COMMIT();

    // ---- fused attention: 4 threads per example (one per head), write fp16 into B1 ----
    {
        int r = tid >> 2;          // 0..63
        int h = tid & 3;
        int ex = R0 + r;
        int p = pv[ex], a = av[ex], b = bv[ex];
        float smv = g_SM[p*NH+h];
        float s0  = g_S0[p*NH+h];
        float s3  = g_S3[p*NH+h];
        float s1  = g_T1[(p*NP+a)*NH+h] + smv;
        float s2  = g_T2[(p*NP+b)*NH+h] + smv;
        float m  = fmaxf(fmaxf(s0,s1),fmaxf(s2,s3));
        float e0=expf(s0-m), e1=expf(s1-m), e2=expf(s2-m), e3=expf(s3-m);
        float inv = 1.f/(e0+e1+e2+e3);
        float w0=e0*inv, w1=e1*inv, w2=e2*inv, w3=e3*inv, w12=w1+w2;
        #pragma unroll
        for (int jj=0; jj<8; jj++){
            int d0 = h*32 + jj*4;
            float4 V0 = *(const float4*)&g_V0 [p*D+d0];
            float4 V3 = *(const float4*)&g_V3 [p*D+d0];
            float4 VM = *(const float4*)&g_VM [p*D+d0];
            float4 Va = *(const float4*)&g_V1T[a*D+d0];
            float4 Vb = *(const float4*)&g_V2T[b*D+d0];
            float o0 = w0*V0.x + w3*V3.x + w12*VM.x + w1*Va.x + w2*Vb.x;
            float o1 = w0*V0.y + w3*V3.y + w12*VM.y + w1*Va.y + w2*Vb.y;
            float o2 = w0*V0.z + w3*V3.z + w12*VM.z + w1*Va.z + w2*Vb.z;
            float o3 = w0*V0.w + w3*V3.w + w12*VM.w + w1*Va.w + w2*Vb.w;
            wpair(B1, r, d0,   o0, o1);
            wpair(B1, r, d0+2, o2, o3);
        }
    }

    if (tid < 64) ps[tid] = pv[R0+tid];
    if (tid < 128) sb2[tid] = b2[tid];
    if (tid < NPAD) sbc[tid] = g_biasC[tid];
    CP_WAIT1();            // g0 (WO) done
    __syncthreads();       // attn image + WO visible

    // ---- stage A: P = attn @ WO ----
    float accA[8][4];
    #pragma unroll
    for (int nt=0;nt<8;nt++){
        #pragma unroll
        for (int q=0;q<4;q++) accA[nt][q]=0.f;
    }
    mma_pass1<8>(accA, b1A, w0A, rowbase, wn*64, lane);
    __syncthreads();       // WB0 free, B1 free

    // g2: W2_0 -> WB0
    for (int i=tid;i<2048;i+=256) cpa16(w0A + i*16u, g_W2img + i);
    CP_COMMIT();

    // ---- x3 = P + X3F[p]; write x3 image (overlaps g2) ----
    {
        int r = rowbase + lr;
        int p0 = ps[r], p1 = ps[r+8];
        #pragma unroll
        for (int nt=0;nt<8;nt++){
            int col = wn*64 + nt*8 + lq*2;
            wpair(X3, r,   col, accA[nt][0] + g_X3F[p0*D+col], accA[nt][1] + g_X3F[p0*D+col+1]);
            wpair(X3, r+8, col, accA[nt][2] + g_X3F[p1*D+col], accA[nt][3] + g_X3F[p1*D+col+1]);
        }
    }
    CP_WAIT1();            // g1 (W1_0) done
    __syncthreads();

    // ---- mlp accumulator (H@W2 summed over chunks) ----
    float accM[8][4];
    #pragma unroll
    for (int nt=0;nt<8;nt++){
        #pragma unroll
        for (int q=0;q<4;q++) accM[nt][q]=0.f;
    }

    for (int ch=0; ch<4; ch++){
        if (tid < 128) sb1[tid] = bias1[ch*128+tid];

        float accH[8][4];
        #pragma unroll
        for (int nt=0;nt<8;nt++){
            #pragma unroll
            for (int q=0;q<4;q++) accH[nt][q]=0.f;
        }
        mma_pass1<8>(accH, x3A, w1A, rowbase, wn*64, lane);
        __syncthreads();   // WB1 free; sb1 visible

        // prefetch into WB1: W1_{ch+1} or Wun
        if (ch < 3){
            for (int i=tid;i<2048;i+=256) cpa16(w1A + i*16u, g_W1img + (size_t)(ch+1)*2048 + i);
        } else {
            for (int i=tid;i<2560;i+=256) cpa16(w1A + i*16u, g_WUimg + i);
        }
        CP_COMMIT();

        // H epilogue -> B1 image (overlaps prefetch)
        {
            int r = rowbase + lr;
            #pragma unroll
            for (int nt=0;nt<8;nt++){
                int col = wn*64 + nt*8 + lq*2;
                float b0 = sb1[col], b1v = sb1[col+1];
                wpair(B1, r,   col, fmaxf(accH[nt][0]+b0,0.f), fmaxf(accH[nt][1]+b1v,0.f));
                wpair(B1, r+8, col, fmaxf(accH[nt][2]+b0,0.f), fmaxf(accH[nt][3]+b1v,0.f));
            }
        }
        CP_WAIT1();        // W2_ch done (in WB0)
        __syncthreads();

        mma_pass1<8>(accM, b1A, w0A, rowbase, wn*64, lane);   // accM += H_ch @ W2_ch
        __syncthreads();   // WB0 free, B1 free

        if (ch < 3){
            for (int i=tid;i<2048;i+=256) cpa16(w0A + i*16u, g_W2img + (size_t)(ch+1)*2048 + i);
            CP_COMMIT();
        }
    }

    // ---- y = x3 + mlp + b2 -> B1 image ----
    {
        int r = rowbase + lr;
        #pragma unroll
        for (int nt=0;nt<8;nt++){
            int col = wn*64 + nt*8 + lq*2;
            float b0 = sb2[col], b1v = sb2[col+1];
            float2 x0 = rpair(X3, r,   col);
            float2 x1 = rpair(X3, r+8, col);
            wpair(B1, r,   col, x0.x + accM[nt][0] + b0, x0.y + accM[nt][1] + b1v);
            wpair(B1, r+8, col, x1.x + accM[nt][2] + b0, x1.y + accM[nt][3] + b1v);
        }
    }
    CP_WAIT0();            // Wun done (in WB1)
    __syncthreads();

    // ---- logits = y @ Wun ----
    float accL[10][4];
    #pragma unroll
    for (int nt=0;nt<10;nt++){
        #pragma unroll
        for (int q=0;q<4;q++) accL[nt][q]=0.f;
    }
    mma_pass1<10>(accL, b1A, w1A, rowbase, wn*80, lane);

    // ---- logits epilogue ----
    {
        int row = R0 + rowbase + lr;
        #pragma unroll
        for (int nt=0;nt<10;nt++){
            int col = wn*80 + nt*8 + lq*2;
            if (col < NOUT){
                out[row*NOUT+col]       = accL[nt][0] + sbc[col];
                out[(row+8)*NOUT+col]   = accL[nt][2] + sbc[col];
            }
            if (col+1 < NOUT){
                out[row*NOUT+col+1]     = accL[nt][1] + sbc[col+1];
                out[(row+8)*NOUT+col+1] = accL[nt][3] + sbc[col+1];
            }
        }
    }
}

// ---------------- launch ----------------
extern "C" void kernel_launch(void* const* d_in, const int* in_sizes, int n_in,
                              void* d_out, int out_size){
    const int*   pv    = (const int*)  d_in[0];
    const int*   av    = (const int*)  d_in[1];
    const int*   bvv   = (const int*)  d_in[2];
    const float* emb   = (const float*)d_in[3];
    const float* pos   = (const float*)d_in[4];
    const float* W_mem = (const float*)d_in[5];
    const float* b_mem = (const float*)d_in[6];
    const float* W_sur = (const float*)d_in[7];
    const float* b_sur = (const float*)d_in[8];
    const float* W_m2r = (const float*)d_in[9];
    const float* b_m2r = (const float*)d_in[10];
    const float* W_Q   = (const float*)d_in[11];
    const float* W_K   = (const float*)d_in[12];
    const float* W_V   = (const float*)d_in[13];
    const float* W_O   = (const float*)d_in[14];
    const float* W1    = (const float*)d_in[15];
    const float* bias1 = (const float*)d_in[16];
    const float* W2    = (const float*)d_in[17];
    const float* b2    = (const float*)d_in[18];
    const float* W_un  = (const float*)d_in[19];
    const float* b_un  = (const float*)d_in[20];
    float* out = (float*)d_out;

    k_precompute<<<NP,128>>>(emb,pos,W_mem,b_mem,W_sur,b_sur,W_m2r,b_m2r,W_Q,W_K,W_V);
    k_ttab<<<NP,128>>>();
    k_wprep<<<1312,128>>>(W_O,W1,W2,W_un,b_un);

    cudaFuncSetAttribute(k_fused, cudaFuncAttributeMaxDynamicSharedMemorySize, FU_SMEM);
    k_fused<<<BB/64,256,FU_SMEM>>>(pv,av,bvv,bias1,b2,out);
}

// round 16
// speedup vs baseline: 1.8682x; 1.8682x over previous
#include <cuda_runtime.h>
#include <cuda_fp16.h>
#include <math.h>
#include <stdint.h>

#define BB 65536
#define D 128
#define NH 4
#define DH 32
#define DMLP 512
#define DMEM 64
#define NP 150
#define EQTOK 151
#define NOUT 150
#define NPAD 160

// ---------------- warp-level fp16 tensor-core mma (fp32 accumulate) ----------------
__device__ __forceinline__ void mma16816(float* c, const uint32_t* a, const uint32_t* b){
    asm volatile(
        "mma.sync.aligned.m16n8k16.row.col.f32.f16.f16.f32 "
        "{%0,%1,%2,%3}, {%4,%5,%6,%7}, {%8,%9}, {%0,%1,%2,%3};"
        : "+f"(c[0]), "+f"(c[1]), "+f"(c[2]), "+f"(c[3])
        : "r"(a[0]), "r"(a[1]), "r"(a[2]), "r"(a[3]), "r"(b[0]), "r"(b[1]));
}
__device__ __forceinline__ void ldsm4(uint32_t* r, uint32_t addr){
    asm volatile("ldmatrix.sync.aligned.m8n8.x4.shared.b16 {%0,%1,%2,%3}, [%4];"
        : "=r"(r[0]), "=r"(r[1]), "=r"(r[2]), "=r"(r[3]) : "r"(addr));
}
__device__ __forceinline__ uint32_t smem_u32(const void* p){
    uint32_t a;
    asm("{ .reg .u64 t; cvta.to.shared.u64 t, %1; cvt.u32.u64 %0, t; }" : "=r"(a) : "l"(p));
    return a;
}
__device__ __forceinline__ void cpa16(uint32_t dst, const void* src){
    asm volatile("cp.async.cg.shared.global [%0], [%1], 16;" :: "r"(dst), "l"(src) : "memory");
}
#define CP_COMMIT() asm volatile("cp.async.commit_group;" ::: "memory")
#define CP_WAIT1()  asm volatile("cp.async.wait_group 1;" ::: "memory")
#define CP_WAIT0()  asm volatile("cp.async.wait_group 0;" ::: "memory")

// ---------------- persistent scratch ----------------
__device__ float g_X3F[NP*D];
__device__ float g_Q3[NP*D];
__device__ float g_S0[NP*NH];
__device__ float g_S3[NP*NH];
__device__ float g_SM[NP*NH];
__device__ float g_K1T[NP*D];
__device__ float g_K2T[NP*D];
__device__ float g_T1[NP*NP*NH];
__device__ float g_T2[NP*NP*NH];
__device__ float g_biasC[NPAD];       // b_un padded
// fp16 V tables (halved k_attn traffic)
__device__ __half g_V0h[NP*D];
__device__ __half g_V3h[NP*D];
__device__ __half g_VMh[NP*D];
__device__ __half g_V1h[NP*D];
__device__ __half g_V2h[NP*D];
// attention-output fp16 images: [512 image-blocks][128 rows x 128 k swizzled = 32KB]
__device__ uint4 g_AttnImg[(size_t)512*2048];
// weight images (fp16, swizzled, B-operand layout: row=output col, col=k)
__device__ uint4 g_WOimg[2048];
__device__ uint4 g_W1img[4*2048];
__device__ uint4 g_W2img[4*2048];     // W2 slabs: rows n(128 model dims), k within slab
__device__ uint4 g_WUimg[2560];       // Wun image: rows n(160 padded), k=128

// image addressing: rows of 256B (128 fp16), 16B chunks XOR-swizzled by (row&7)
__device__ __forceinline__ unsigned img_off_elem(int r, int k){
    return (unsigned)r*256u + ((((unsigned)k>>3)^((unsigned)r&7u))*16u) + ((unsigned)k&7u)*2u;
}
// f32 pair -> fp16, 4-byte write at (r, col even)
__device__ __forceinline__ void wpair(char* img, int r, int col, float a, float b){
    __half h0=__float2half(a), h1=__float2half(b);
    unsigned off = (unsigned)r*256u + ((((unsigned)col>>3)^((unsigned)r&7u))*16u) + ((unsigned)col&7u)*2u;
    unsigned hv = (unsigned)*(unsigned short*)&h0 | ((unsigned)*(unsigned short*)&h1<<16);
    *(unsigned*)(img+off)=hv;
}
// read fp16 pair at (r, col even)
__device__ __forceinline__ float2 rpair(const char* img, int r, int col){
    unsigned off = (unsigned)r*256u + ((((unsigned)col>>3)^((unsigned)r&7u))*16u) + ((unsigned)col&7u)*2u;
    __half2 h = *(const __half2*)(img+off);
    return __half22float2(h);
}
// load 4 halves -> 4 floats
__device__ __forceinline__ void ld4h(const __half* p, float* o){
    uint2 v = *(const uint2*)p;
    float2 a = __half22float2(*(__half2*)&v.x);
    float2 b = __half22float2(*(__half2*)&v.y);
    o[0]=a.x; o[1]=a.y; o[2]=b.x; o[3]=b.y;
}

// ---------------- merged prep: weight images (bx<1312) + per-p tables (bx>=1312) ----------------
__global__ void k_prep(
    const float* __restrict__ WO, const float* __restrict__ W1,
    const float* __restrict__ W2, const float* __restrict__ Wun,
    const float* __restrict__ b_un,
    const float* __restrict__ emb, const float* __restrict__ pos,
    const float* __restrict__ W_mem, const float* __restrict__ b_mem,
    const float* __restrict__ W_sur, const float* __restrict__ b_sur,
    const float* __restrict__ W_m2r, const float* __restrict__ b_m2r,
    const float* __restrict__ W_Q, const float* __restrict__ W_K,
    const float* __restrict__ W_V)
{
    int bx = blockIdx.x;
    if (bx < 1312){
        int k  = threadIdx.x;    // 0..127
        float val; char* img; int rowc;
        if (bx < 128){
            rowc = bx;
            val = WO[k*D + rowc];
            img = (char*)g_WOimg;
        } else if (bx < 640){
            int idx = bx - 128;
            int ch = idx >> 7, j = idx & 127;
            rowc = j;
            val = W1[k*DMLP + ch*128 + j];
            img = (char*)g_W1img + (size_t)ch*32768;
        } else if (bx < 1152){
            int idx = bx - 640;
            int ch = idx >> 7, n = idx & 127;
            rowc = n;
            val = W2[(ch*128 + k)*D + n];
            img = (char*)g_W2img + (size_t)ch*32768;
        } else {
            int n = bx - 1152;   // 0..159
            rowc = n;
            val = (n < NOUT) ? Wun[k*NOUT + n] : 0.f;
            img = (char*)g_WUimg;
            if (k == 0) g_biasC[n] = (n < NOUT) ? b_un[n] : 0.f;
        }
        __half h = __float2half(val);
        unsigned off = img_off_elem(rowc, k);
        *(unsigned short*)(img + off) = *(unsigned short*)&h;
        return;
    }

    int p = bx - 1312;           // 0..149
    int d = threadIdx.x;         // 128 threads
    __shared__ float x0f[D], zz[DMEM], diffs[D], zu[DMEM], memv[D];
    __shared__ float x0full[D], x3full[D];
    __shared__ float sq[D], sk0[D], sk3[D], skm[D], e1v[D], e2v[D];

    x0f[d] = emb[p*D+d] + pos[d];
    __syncthreads();
    if (d < DMEM){
        float acc = b_mem[d];
        for (int e=0;e<D;e++) acc += x0f[e]*W_mem[e*DMEM+d];
        zz[d] = acc/(1.f+expf(-acc));        // silu
    }
    __syncthreads();
    {
        float pr = b_sur[d];
        for (int j=0;j<DMEM;j++) pr += zz[j]*W_sur[j*D+d];
        diffs[d] = x0f[d] - pr;
    }
    __syncthreads();
    if (d < DMEM){
        float acc = 0.f;
        for (int e=0;e<D;e++) acc += diffs[e]*W_mem[e*DMEM+d];
        zu[d] = zz[d] + acc/(1.f+expf(-acc));
    }
    __syncthreads();
    {
        float mm = b_m2r[d];
        for (int j=0;j<DMEM;j++) mm += zu[j]*W_m2r[j*D+d];
        memv[d]  = mm;
        x0full[d] = x0f[d] + mm;
        x3full[d] = emb[EQTOK*D+d] + pos[3*D+d] + mm;
        e1v[d] = emb[p*D+d] + pos[D+d];
        e2v[d] = emb[p*D+d] + pos[2*D+d];
    }
    __syncthreads();

    int h = d>>5;
    const float* Wq = W_Q + h*D*DH + (d&31);
    const float* Wk = W_K + h*D*DH + (d&31);
    const float* Wv = W_V + h*D*DH + (d&31);
    float q=0,k0=0,k3=0,km=0,v0=0,v3=0,vm=0,k1=0,v1=0,k2=0,v2=0;
    for (int e=0;e<D;e++){
        float wq=Wq[e*DH], wk=Wk[e*DH], wv=Wv[e*DH];
        q  += x3full[e]*wq;
        k0 += x0full[e]*wk; k3 += x3full[e]*wk; km += memv[e]*wk;
        v0 += x0full[e]*wv; v3 += x3full[e]*wv; vm += memv[e]*wv;
        k1 += e1v[e]*wk;    v1 += e1v[e]*wv;
        k2 += e2v[e]*wk;    v2 += e2v[e]*wv;
    }
    q *= 0.17677669529663687f;  // 1/sqrt(32)
    g_Q3[p*D+d]=q;  g_X3F[p*D+d]=x3full[d];
    g_V0h[p*D+d]=__float2half(v0);
    g_V3h[p*D+d]=__float2half(v3);
    g_VMh[p*D+d]=__float2half(vm);
    g_V1h[p*D+d]=__float2half(v1);
    g_V2h[p*D+d]=__float2half(v2);
    g_K1T[p*D+d]=k1; g_K2T[p*D+d]=k2;
    sq[d]=q; sk0[d]=k0; sk3[d]=k3; skm[d]=km;
    __syncthreads();
    if (d < 3*NH){
        int hh = d & 3, which = d >> 2;
        const float* kk = (which==0) ? sk0 : (which==1 ? sk3 : skm);
        float acc=0.f;
        for (int t=0;t<DH;t++) acc += sq[hh*DH+t]*kk[hh*DH+t];
        float* dst = (which==0) ? g_S0 : (which==1 ? g_S3 : g_SM);
        dst[p*NH+hh] = acc;
    }
}

// ---------------- bilinear score tables T1/T2 ----------------
__global__ void k_ttab(){
    int p = blockIdx.x;
    __shared__ float q[D];
    int t = threadIdx.x;
    q[t] = g_Q3[p*D+t];
    __syncthreads();
    for (int a=t; a<NP; a+=128){
        for (int h=0;h<NH;h++){
            float s1=0.f, s2=0.f;
            for (int k=0;k<DH;k++){
                float qv = q[h*DH+k];
                s1 += qv*g_K1T[a*D+h*DH+k];
                s2 += qv*g_K2T[a*D+h*DH+k];
            }
            g_T1[(p*NP+a)*NH+h] = s1;
            g_T2[(p*NP+a)*NH+h] = s2;
        }
    }
}

// ---------------- per-example attention; fp16 tables; writes fp16 images ----------------
__global__ void k_attn(const int* __restrict__ pv, const int* __restrict__ av,
                       const int* __restrict__ bv){
    int idx  = blockIdx.x*blockDim.x + threadIdx.x;
    int ex   = idx >> 5;
    int lane = idx & 31;
    int p = pv[ex], a = av[ex], b = bv[ex];
    int h = lane >> 3;
    float smv = g_SM[p*NH+h];
    float s0  = g_S0[p*NH+h];
    float s3  = g_S3[p*NH+h];
    float s1  = g_T1[(p*NP+a)*NH+h] + smv;
    float s2  = g_T2[(p*NP+b)*NH+h] + smv;
    float m  = fmaxf(fmaxf(s0,s1),fmaxf(s2,s3));
    float e0=expf(s0-m), e1=expf(s1-m), e2=expf(s2-m), e3=expf(s3-m);
    float inv = 1.f/(e0+e1+e2+e3);
    float w0=e0*inv, w1=e1*inv, w2=e2*inv, w3=e3*inv, w12=w1+w2;
    int d0 = lane*4;
    float V0[4], V3[4], VM[4], Va[4], Vb[4];
    ld4h(g_V0h + p*D + d0, V0);
    ld4h(g_V3h + p*D + d0, V3);
    ld4h(g_VMh + p*D + d0, VM);
    ld4h(g_V1h + a*D + d0, Va);
    ld4h(g_V2h + b*D + d0, Vb);
    union { unsigned short s[4]; uint2 q; } H;
    #pragma unroll
    for (int j=0;j<4;j++){
        float o = w0*V0[j] + w3*V3[j] + w12*VM[j] + w1*Va[j] + w2*Vb[j];
        __half hh = __float2half(o);
        H.s[j] = *(unsigned short*)&hh;
    }
    int blkimg = ex >> 7, r = ex & 127;
    unsigned off = (unsigned)r*256u + ((((unsigned)d0>>3)^((unsigned)r&7u))*16u) + ((unsigned)d0&7u)*2u;
    *(uint2*)((char*)g_AttnImg + (size_t)blkimg*32768 + off) = H.q;
}

// ---------------- single-M-tile MMA pass via ldmatrix (fp32 accumulate) ----------------
template<int NT>
__device__ __forceinline__ void mma_pass1(float (&acc)[NT][4], uint32_t Aimg, uint32_t Bimg,
                                          int rowbase, int colbase, int lane){
    int q = lane >> 3, j = lane & 7;
    unsigned rA = (unsigned)(rowbase + ((q&1)<<3) + j);
    unsigned rA7 = rA & 7u, chselA = (unsigned)(q>>1);
    unsigned baseA = Aimg + rA*256u;
    unsigned rB = (unsigned)(colbase + ((q>>1)<<3) + j);
    unsigned rB7 = rB & 7u, chselB = (unsigned)(q&1);
    unsigned baseB = Bimg + rB*256u;
    #pragma unroll
    for (int ks=0; ks<8; ks++){
        unsigned offA = ((((unsigned)ks*2u + chselA) ^ rA7) << 4);
        uint32_t afr[4];
        ldsm4(afr, baseA + offA);
        unsigned offB = ((((unsigned)ks*2u + chselB) ^ rB7) << 4);
        uint32_t bfr[NT][2];
        #pragma unroll
        for (int c=0; c<NT/2; c++){
            uint32_t t[4];
            ldsm4(t, baseB + (unsigned)c*4096u + offB);
            bfr[2*c][0]=t[0]; bfr[2*c][1]=t[1]; bfr[2*c+1][0]=t[2]; bfr[2*c+1][1]=t[3];
        }
        #pragma unroll
        for (int nt=0; nt<NT; nt++) mma16816(acc[nt], afr, bfr[nt]);
    }
}

// ---------------- fused GEMM chain: M=64 per CTA, 2 CTAs/SM ----------------
#define OFF_X3  16384
#define OFF_WB0 32768
#define OFF_WB1 65536
#define FU_SMEM (65536+40960)

__global__ void __launch_bounds__(256,2)
k_fused(const int* __restrict__ pv, const float* __restrict__ bias1,
        const float* __restrict__ b2, float* __restrict__ out){
    extern __shared__ char sm[];
    char* B1  = sm;                // 16KB: attn half-image, later H-chunk / y images (64 rows)
    char* X3  = sm + OFF_X3;       // 16KB: x3 image (64 rows)
    char* WB0 = sm + OFF_WB0;      // 32KB weight buffer 0 (WO, W2 slabs)
    char* WB1 = sm + OFF_WB1;      // 40KB weight buffer 1 (W1 slabs, Wun)
    __shared__ int ps[64];
    __shared__ float sb1[128];
    __shared__ float sb2[128];
    __shared__ float sbc[NPAD];

    uint32_t b1A = smem_u32(B1), x3A = smem_u32(X3), w0A = smem_u32(WB0), w1A = smem_u32(WB1);

    int tid = threadIdx.x, wid = tid>>5, lane = tid&31;
    int blk = blockIdx.x;          // 0..1023, 64 rows each
    int R0  = blk*64;
    int wm = wid & 3, wn = wid >> 2;       // 4 M-groups x 2 N-groups
    int lr = lane >> 2, lq = lane & 3;
    int rowbase = wm*16;

    // g0: attn half-image -> B1, WO -> WB0
    {
        const uint4* sA = g_AttnImg + (size_t)(blk>>1)*2048 + (size_t)(blk&1)*1024;
        for (int i=tid;i<1024;i+=256) cpa16(b1A + i*16u, sA + i);
        for (int i=tid;i<2048;i+=256) cpa16(w0A + i*16u, g_WOimg + i);
        CP_COMMIT();
    }
    // g1: W1_0 -> WB1
    for (int i=tid;i<2048;i+=256) cpa16(w1A + i*16u, g_W1img + i);
    CP_COMMIT();

    if (tid < 64) ps[tid] = pv[R0+tid];
    if (tid < 128) sb2[tid] = b2[tid];
    if (tid < NPAD) sbc[tid] = g_biasC[tid];
    CP_WAIT1();            // g0 done
    __syncthreads();

    // ---- stage A: P = attn @ WO ----
    float accA[8][4];
    #pragma unroll
    for (int nt=0;nt<8;nt++){
        #pragma unroll
        for (int q=0;q<4;q++) accA[nt][q]=0.f;
    }
    mma_pass1<8>(accA, b1A, w0A, rowbase, wn*64, lane);
    __syncthreads();       // WB0 free, B1 free

    // g2: W2_0 -> WB0
    for (int i=tid;i<2048;i+=256) cpa16(w0A + i*16u, g_W2img + i);
    CP_COMMIT();

    // ---- x3 = P + X3F[p]; write x3 image (overlaps g2) ----
    {
        int r = rowbase + lr;
        int p0 = ps[r], p1 = ps[r+8];
        #pragma unroll
        for (int nt=0;nt<8;nt++){
            int col = wn*64 + nt*8 + lq*2;
            wpair(X3, r,   col, accA[nt][0] + g_X3F[p0*D+col], accA[nt][1] + g_X3F[p0*D+col+1]);
            wpair(X3, r+8, col, accA[nt][2] + g_X3F[p1*D+col], accA[nt][3] + g_X3F[p1*D+col+1]);
        }
    }
    CP_WAIT1();            // g1 (W1_0) done
    __syncthreads();

    // ---- mlp accumulator (H@W2 summed over chunks) ----
    float accM[8][4];
    #pragma unroll
    for (int nt=0;nt<8;nt++){
        #pragma unroll
        for (int q=0;q<4;q++) accM[nt][q]=0.f;
    }

    for (int ch=0; ch<4; ch++){
        if (tid < 128) sb1[tid] = bias1[ch*128+tid];

        float accH[8][4];
        #pragma unroll
        for (int nt=0;nt<8;nt++){
            #pragma unroll
            for (int q=0;q<4;q++) accH[nt][q]=0.f;
        }
        mma_pass1<8>(accH, x3A, w1A, rowbase, wn*64, lane);
        __syncthreads();   // WB1 free; sb1 visible

        // prefetch into WB1: W1_{ch+1} or Wun
        if (ch < 3){
            for (int i=tid;i<2048;i+=256) cpa16(w1A + i*16u, g_W1img + (size_t)(ch+1)*2048 + i);
        } else {
            for (int i=tid;i<2560;i+=256) cpa16(w1A + i*16u, g_WUimg + i);
        }
        CP_COMMIT();

        // H epilogue -> B1 image (overlaps prefetch)
        {
            int r = rowbase + lr;
            #pragma unroll
            for (int nt=0;nt<8;nt++){
                int col = wn*64 + nt*8 + lq*2;
                float b0 = sb1[col], b1v = sb1[col+1];
                wpair(B1, r,   col, fmaxf(accH[nt][0]+b0,0.f), fmaxf(accH[nt][1]+b1v,0.f));
                wpair(B1, r+8, col, fmaxf(accH[nt][2]+b0,0.f), fmaxf(accH[nt][3]+b1v,0.f));
            }
        }
        CP_WAIT1();        // W2_ch done (in WB0)
        __syncthreads();

        mma_pass1<8>(accM, b1A, w0A, rowbase, wn*64, lane);   // accM += H_ch @ W2_ch
        __syncthreads();   // WB0 free, B1 free

        if (ch < 3){
            for (int i=tid;i<2048;i+=256) cpa16(w0A + i*16u, g_W2img + (size_t)(ch+1)*2048 + i);
            CP_COMMIT();
        }
    }

    // ---- y = x3 + mlp + b2 -> B1 image ----
    {
        int r = rowbase + lr;
        #pragma unroll
        for (int nt=0;nt<8;nt++){
            int col = wn*64 + nt*8 + lq*2;
            float b0 = sb2[col], b1v = sb2[col+1];
            float2 x0 = rpair(X3, r,   col);
            float2 x1 = rpair(X3, r+8, col);
            wpair(B1, r,   col, x0.x + accM[nt][0] + b0, x0.y + accM[nt][1] + b1v);
            wpair(B1, r+8, col, x1.x + accM[nt][2] + b0, x1.y + accM[nt][3] + b1v);
        }
    }
    CP_WAIT0();            // Wun done (in WB1)
    __syncthreads();

    // ---- logits = y @ Wun ----
    float accL[10][4];
    #pragma unroll
    for (int nt=0;nt<10;nt++){
        #pragma unroll
        for (int q=0;q<4;q++) accL[nt][q]=0.f;
    }
    mma_pass1<10>(accL, b1A, w1A, rowbase, wn*80, lane);

    // ---- logits epilogue ----
    {
        int row = R0 + rowbase + lr;
        #pragma unroll
        for (int nt=0;nt<10;nt++){
            int col = wn*80 + nt*8 + lq*2;
            if (col < NOUT){
                out[row*NOUT+col]       = accL[nt][0] + sbc[col];
                out[(row+8)*NOUT+col]   = accL[nt][2] + sbc[col];
            }
            if (col+1 < NOUT){
                out[row*NOUT+col+1]     = accL[nt][1] + sbc[col+1];
                out[(row+8)*NOUT+col+1] = accL[nt][3] + sbc[col+1];
            }
        }
    }
}

// ---------------- launch ----------------
extern "C" void kernel_launch(void* const* d_in, const int* in_sizes, int n_in,
                              void* d_out, int out_size){
    const int*   pv    = (const int*)  d_in[0];
    const int*   av    = (const int*)  d_in[1];
    const int*   bvv   = (const int*)  d_in[2];
    const float* emb   = (const float*)d_in[3];
    const float* pos   = (const float*)d_in[4];
    const float* W_mem = (const float*)d_in[5];
    const float* b_mem = (const float*)d_in[6];
    const float* W_sur = (const float*)d_in[7];
    const float* b_sur = (const float*)d_in[8];
    const float* W_m2r = (const float*)d_in[9];
    const float* b_m2r = (const float*)d_in[10];
    const float* W_Q   = (const float*)d_in[11];
    const float* W_K   = (const float*)d_in[12];
    const float* W_V   = (const float*)d_in[13];
    const float* W_O   = (const float*)d_in[14];
    const float* W1    = (const float*)d_in[15];
    const float* bias1 = (const float*)d_in[16];
    const float* W2    = (const float*)d_in[17];
    const float* b2    = (const float*)d_in[18];
    const float* W_un  = (const float*)d_in[19];
    const float* b_un  = (const float*)d_in[20];
    float* out = (float*)d_out;

    k_prep<<<1312+NP,128>>>(W_O,W1,W2,W_un,b_un,
                            emb,pos,W_mem,b_mem,W_sur,b_sur,W_m2r,b_m2r,W_Q,W_K,W_V);
    k_ttab<<<NP,128>>>();
    k_attn<<<BB/8,256>>>(pv,av,bvv);

    cudaFuncSetAttribute(k_fused, cudaFuncAttributeMaxDynamicSharedMemorySize, FU_SMEM);
    k_fused<<<BB/64,256,FU_SMEM>>>(pv,bias1,b2,out);
}

// round 17
// speedup vs baseline: 1.9659x; 1.0523x over previous
#include <cuda_runtime.h>
#include <cuda_fp16.h>
#include <math.h>
#include <stdint.h>

#define BB 65536
#define D 128
#define NH 4
#define DH 32
#define DMLP 512
#define DMEM 64
#define NP 150
#define EQTOK 151
#define NOUT 150
#define NPAD 160

// ---------------- warp-level fp16 tensor-core mma (fp32 accumulate) ----------------
__device__ __forceinline__ void mma16816(float* c, const uint32_t* a, const uint32_t* b){
    asm volatile(
        "mma.sync.aligned.m16n8k16.row.col.f32.f16.f16.f32 "
        "{%0,%1,%2,%3}, {%4,%5,%6,%7}, {%8,%9}, {%0,%1,%2,%3};"
        : "+f"(c[0]), "+f"(c[1]), "+f"(c[2]), "+f"(c[3])
        : "r"(a[0]), "r"(a[1]), "r"(a[2]), "r"(a[3]), "r"(b[0]), "r"(b[1]));
}
__device__ __forceinline__ void ldsm4(uint32_t* r, uint32_t addr){
    asm volatile("ldmatrix.sync.aligned.m8n8.x4.shared.b16 {%0,%1,%2,%3}, [%4];"
        : "=r"(r[0]), "=r"(r[1]), "=r"(r[2]), "=r"(r[3]) : "r"(addr));
}
__device__ __forceinline__ uint32_t smem_u32(const void* p){
    uint32_t a;
    asm("{ .reg .u64 t; cvta.to.shared.u64 t, %1; cvt.u32.u64 %0, t; }" : "=r"(a) : "l"(p));
    return a;
}
__device__ __forceinline__ void cpa16(uint32_t dst, const void* src){
    asm volatile("cp.async.cg.shared.global [%0], [%1], 16;" :: "r"(dst), "l"(src) : "memory");
}
#define CP_COMMIT() asm volatile("cp.async.commit_group;" ::: "memory")
#define CP_WAIT1()  asm volatile("cp.async.wait_group 1;" ::: "memory")
#define CP_WAIT0()  asm volatile("cp.async.wait_group 0;" ::: "memory")

// ---------------- persistent scratch ----------------
__device__ float g_X3F[NP*D];
__device__ float g_Q3[NP*D];
__device__ float g_S0[NP*NH];
__device__ float g_S3[NP*NH];
__device__ float g_SM[NP*NH];
__device__ float g_K1T[NP*D];
__device__ float g_K2T[NP*D];
__device__ float g_T1[NP*NP*NH];
__device__ float g_T2[NP*NP*NH];
__device__ float g_biasC[NPAD];       // b_un padded
// fp16 V tables
__device__ __half g_V0h[NP*D];
__device__ __half g_V3h[NP*D];
__device__ __half g_VMh[NP*D];
__device__ __half g_V1h[NP*D];
__device__ __half g_V2h[NP*D];
// attention-output fp16 images: [512 image-blocks][128 rows x 128 k swizzled = 32KB]
__device__ uint4 g_AttnImg[(size_t)512*2048];
// weight images (fp16, swizzled, B-operand layout: row=output col, col=k)
__device__ uint4 g_WOimg[2048];
__device__ uint4 g_W1img[4*2048];
__device__ uint4 g_W2img[4*2048];
__device__ uint4 g_WUimg[2560];

// image addressing: rows of 256B (128 fp16), 16B chunks XOR-swizzled by (row&7)
__device__ __forceinline__ unsigned img_off_elem(int r, int k){
    return (unsigned)r*256u + ((((unsigned)k>>3)^((unsigned)r&7u))*16u) + ((unsigned)k&7u)*2u;
}
__device__ __forceinline__ void wpair(char* img, int r, int col, float a, float b){
    __half h0=__float2half(a), h1=__float2half(b);
    unsigned off = (unsigned)r*256u + ((((unsigned)col>>3)^((unsigned)r&7u))*16u) + ((unsigned)col&7u)*2u;
    unsigned hv = (unsigned)*(unsigned short*)&h0 | ((unsigned)*(unsigned short*)&h1<<16);
    *(unsigned*)(img+off)=hv;
}
__device__ __forceinline__ float2 rpair(const char* img, int r, int col){
    unsigned off = (unsigned)r*256u + ((((unsigned)col>>3)^((unsigned)r&7u))*16u) + ((unsigned)col&7u)*2u;
    __half2 h = *(const __half2*)(img+off);
    return __half22float2(h);
}
__device__ __forceinline__ void ld4h(const __half* p, float* o){
    uint2 v = *(const uint2*)p;
    float2 a = __half22float2(*(__half2*)&v.x);
    float2 b = __half22float2(*(__half2*)&v.y);
    o[0]=a.x; o[1]=a.y; o[2]=b.x; o[3]=b.y;
}

// ---------------- merged prep: weight images (bx<1312) + per-p tables (bx>=1312) ----------------
__global__ void k_prep(
    const float* __restrict__ WO, const float* __restrict__ W1,
    const float* __restrict__ W2, const float* __restrict__ Wun,
    const float* __restrict__ b_un,
    const float* __restrict__ emb, const float* __restrict__ pos,
    const float* __restrict__ W_mem, const float* __restrict__ b_mem,
    const float* __restrict__ W_sur, const float* __restrict__ b_sur,
    const float* __restrict__ W_m2r, const float* __restrict__ b_m2r,
    const float* __restrict__ W_Q, const float* __restrict__ W_K,
    const float* __restrict__ W_V)
{
    int bx = blockIdx.x;
    if (bx < 1312){
        int k  = threadIdx.x;    // 0..127
        float val; char* img; int rowc;
        if (bx < 128){
            rowc = bx;
            val = WO[k*D + rowc];
            img = (char*)g_WOimg;
        } else if (bx < 640){
            int idx = bx - 128;
            int ch = idx >> 7, j = idx & 127;
            rowc = j;
            val = W1[k*DMLP + ch*128 + j];
            img = (char*)g_W1img + (size_t)ch*32768;
        } else if (bx < 1152){
            int idx = bx - 640;
            int ch = idx >> 7, n = idx & 127;
            rowc = n;
            val = W2[(ch*128 + k)*D + n];
            img = (char*)g_W2img + (size_t)ch*32768;
        } else {
            int n = bx - 1152;   // 0..159
            rowc = n;
            val = (n < NOUT) ? Wun[k*NOUT + n] : 0.f;
            img = (char*)g_WUimg;
            if (k == 0) g_biasC[n] = (n < NOUT) ? b_un[n] : 0.f;
        }
        __half h = __float2half(val);
        unsigned off = img_off_elem(rowc, k);
        *(unsigned short*)(img + off) = *(unsigned short*)&h;
        return;
    }

    int p = bx - 1312;           // 0..149
    int d = threadIdx.x;         // 128 threads
    __shared__ float x0f[D], zz[DMEM], diffs[D], zu[DMEM], memv[D];
    __shared__ float x0full[D], x3full[D];
    __shared__ float sq[D], sk0[D], sk3[D], skm[D], e1v[D], e2v[D];

    x0f[d] = emb[p*D+d] + pos[d];
    __syncthreads();
    if (d < DMEM){
        float acc = b_mem[d];
        for (int e=0;e<D;e++) acc += x0f[e]*W_mem[e*DMEM+d];
        zz[d] = acc/(1.f+expf(-acc));        // silu
    }
    __syncthreads();
    {
        float pr = b_sur[d];
        for (int j=0;j<DMEM;j++) pr += zz[j]*W_sur[j*D+d];
        diffs[d] = x0f[d] - pr;
    }
    __syncthreads();
    if (d < DMEM){
        float acc = 0.f;
        for (int e=0;e<D;e++) acc += diffs[e]*W_mem[e*DMEM+d];
        zu[d] = zz[d] + acc/(1.f+expf(-acc));
    }
    __syncthreads();
    {
        float mm = b_m2r[d];
        for (int j=0;j<DMEM;j++) mm += zu[j]*W_m2r[j*D+d];
        memv[d]  = mm;
        x0full[d] = x0f[d] + mm;
        x3full[d] = emb[EQTOK*D+d] + pos[3*D+d] + mm;
        e1v[d] = emb[p*D+d] + pos[D+d];
        e2v[d] = emb[p*D+d] + pos[2*D+d];
    }
    __syncthreads();

    int h = d>>5;
    const float* Wq = W_Q + h*D*DH + (d&31);
    const float* Wk = W_K + h*D*DH + (d&31);
    const float* Wv = W_V + h*D*DH + (d&31);
    float q=0,k0=0,k3=0,km=0,v0=0,v3=0,vm=0,k1=0,v1=0,k2=0,v2=0;
    for (int e=0;e<D;e++){
        float wq=Wq[e*DH], wk=Wk[e*DH], wv=Wv[e*DH];
        q  += x3full[e]*wq;
        k0 += x0full[e]*wk; k3 += x3full[e]*wk; km += memv[e]*wk;
        v0 += x0full[e]*wv; v3 += x3full[e]*wv; vm += memv[e]*wv;
        k1 += e1v[e]*wk;    v1 += e1v[e]*wv;
        k2 += e2v[e]*wk;    v2 += e2v[e]*wv;
    }
    q *= 0.17677669529663687f;  // 1/sqrt(32)
    g_Q3[p*D+d]=q;  g_X3F[p*D+d]=x3full[d];
    g_V0h[p*D+d]=__float2half(v0);
    g_V3h[p*D+d]=__float2half(v3);
    g_VMh[p*D+d]=__float2half(vm);
    g_V1h[p*D+d]=__float2half(v1);
    g_V2h[p*D+d]=__float2half(v2);
    g_K1T[p*D+d]=k1; g_K2T[p*D+d]=k2;
    sq[d]=q; sk0[d]=k0; sk3[d]=k3; skm[d]=km;
    __syncthreads();
    if (d < 3*NH){
        int hh = d & 3, which = d >> 2;
        const float* kk = (which==0) ? sk0 : (which==1 ? sk3 : skm);
        float acc=0.f;
        for (int t=0;t<DH;t++) acc += sq[hh*DH+t]*kk[hh*DH+t];
        float* dst = (which==0) ? g_S0 : (which==1 ? g_S3 : g_SM);
        dst[p*NH+hh] = acc;
    }
}

// ---------------- bilinear score tables T1/T2 ----------------
__global__ void k_ttab(){
    int p = blockIdx.x;
    __shared__ float q[D];
    int t = threadIdx.x;
    q[t] = g_Q3[p*D+t];
    __syncthreads();
    for (int a=t; a<NP; a+=128){
        for (int h=0;h<NH;h++){
            float s1=0.f, s2=0.f;
            for (int k=0;k<DH;k++){
                float qv = q[h*DH+k];
                s1 += qv*g_K1T[a*D+h*DH+k];
                s2 += qv*g_K2T[a*D+h*DH+k];
            }
            g_T1[(p*NP+a)*NH+h] = s1;
            g_T2[(p*NP+a)*NH+h] = s2;
        }
    }
}

// ---------------- per-example attention; fp16 tables; writes fp16 images ----------------
__global__ void k_attn(const int* __restrict__ pv, const int* __restrict__ av,
                       const int* __restrict__ bv){
    int idx  = blockIdx.x*blockDim.x + threadIdx.x;
    int ex   = idx >> 5;
    int lane = idx & 31;
    int p = pv[ex], a = av[ex], b = bv[ex];
    int h = lane >> 3;
    float smv = g_SM[p*NH+h];
    float s0  = g_S0[p*NH+h];
    float s3  = g_S3[p*NH+h];
    float s1  = g_T1[(p*NP+a)*NH+h] + smv;
    float s2  = g_T2[(p*NP+b)*NH+h] + smv;
    float m  = fmaxf(fmaxf(s0,s1),fmaxf(s2,s3));
    float e0=expf(s0-m), e1=expf(s1-m), e2=expf(s2-m), e3=expf(s3-m);
    float inv = 1.f/(e0+e1+e2+e3);
    float w0=e0*inv, w1=e1*inv, w2=e2*inv, w3=e3*inv, w12=w1+w2;
    int d0 = lane*4;
    float V0[4], V3[4], VM[4], Va[4], Vb[4];
    ld4h(g_V0h + p*D + d0, V0);
    ld4h(g_V3h + p*D + d0, V3);
    ld4h(g_VMh + p*D + d0, VM);
    ld4h(g_V1h + a*D + d0, Va);
    ld4h(g_V2h + b*D + d0, Vb);
    union { unsigned short s[4]; uint2 q; } H;
    #pragma unroll
    for (int j=0;j<4;j++){
        float o = w0*V0[j] + w3*V3[j] + w12*VM[j] + w1*Va[j] + w2*Vb[j];
        __half hh = __float2half(o);
        H.s[j] = *(unsigned short*)&hh;
    }
    int blkimg = ex >> 7, r = ex & 127;
    unsigned off = (unsigned)r*256u + ((((unsigned)d0>>3)^((unsigned)r&7u))*16u) + ((unsigned)d0&7u)*2u;
    *(uint2*)((char*)g_AttnImg + (size_t)blkimg*32768 + off) = H.q;
}

// ---------------- MMA passes via ldmatrix (fp32 accumulate) ----------------
// 4M x 2N mapping: 1 M-tile of 16 rows per warp, NT col-tiles (used for logits N=160)
template<int NT>
__device__ __forceinline__ void mma_pass1(float (&acc)[NT][4], uint32_t Aimg, uint32_t Bimg,
                                          int rowbase, int colbase, int lane){
    int q = lane >> 3, j = lane & 7;
    unsigned rA = (unsigned)(rowbase + ((q&1)<<3) + j);
    unsigned rA7 = rA & 7u, chselA = (unsigned)(q>>1);
    unsigned baseA = Aimg + rA*256u;
    unsigned rB = (unsigned)(colbase + ((q>>1)<<3) + j);
    unsigned rB7 = rB & 7u, chselB = (unsigned)(q&1);
    unsigned baseB = Bimg + rB*256u;
    #pragma unroll
    for (int ks=0; ks<8; ks++){
        unsigned offA = ((((unsigned)ks*2u + chselA) ^ rA7) << 4);
        uint32_t afr[4];
        ldsm4(afr, baseA + offA);
        unsigned offB = ((((unsigned)ks*2u + chselB) ^ rB7) << 4);
        uint32_t bfr[NT][2];
        #pragma unroll
        for (int c=0; c<NT/2; c++){
            uint32_t t[4];
            ldsm4(t, baseB + (unsigned)c*4096u + offB);
            bfr[2*c][0]=t[0]; bfr[2*c][1]=t[1]; bfr[2*c+1][0]=t[2]; bfr[2*c+1][1]=t[3];
        }
        #pragma unroll
        for (int nt=0; nt<NT; nt++) mma16816(acc[nt], afr, bfr[nt]);
    }
}
// 2M x 4N mapping: 2 M-tiles (32 rows) per warp, NT=4 col-tiles (32 cols) — 64B/lane/ks
template<int NT>
__device__ __forceinline__ void mma_pass2(float (&acc)[2][NT][4], uint32_t Aimg, uint32_t Bimg,
                                          int rowbase, int colbase, int lane){
    int q = lane >> 3, j = lane & 7;
    unsigned rA0 = (unsigned)(rowbase + ((q&1)<<3) + j);
    unsigned rA1 = rA0 + 16u;
    unsigned rA07 = rA0 & 7u, rA17 = rA1 & 7u, chselA = (unsigned)(q>>1);
    unsigned baseA0 = Aimg + rA0*256u;
    unsigned baseA1 = Aimg + rA1*256u;
    unsigned rB = (unsigned)(colbase + ((q>>1)<<3) + j);
    unsigned rB7 = rB & 7u, chselB = (unsigned)(q&1);
    unsigned baseB = Bimg + rB*256u;
    #pragma unroll
    for (int ks=0; ks<8; ks++){
        unsigned kA = (unsigned)ks*2u + chselA;
        uint32_t a0[4], a1[4];
        ldsm4(a0, baseA0 + (((kA ^ rA07) << 4)));
        ldsm4(a1, baseA1 + (((kA ^ rA17) << 4)));
        unsigned offB = ((((unsigned)ks*2u + chselB) ^ rB7) << 4);
        uint32_t bfr[NT][2];
        #pragma unroll
        for (int c=0; c<NT/2; c++){
            uint32_t t[4];
            ldsm4(t, baseB + (unsigned)c*4096u + offB);
            bfr[2*c][0]=t[0]; bfr[2*c][1]=t[1]; bfr[2*c+1][0]=t[2]; bfr[2*c+1][1]=t[3];
        }
        #pragma unroll
        for (int nt=0; nt<NT; nt++){
            mma16816(acc[0][nt], a0, bfr[nt]);
            mma16816(acc[1][nt], a1, bfr[nt]);
        }
    }
}

// ---------------- fused GEMM chain: M=64 per CTA, 2 CTAs/SM ----------------
#define OFF_X3  16384
#define OFF_WB0 32768
#define OFF_WB1 65536
#define FU_SMEM (65536+40960)

__global__ void __launch_bounds__(256,2)
k_fused(const int* __restrict__ pv, const float* __restrict__ bias1,
        const float* __restrict__ b2, float* __restrict__ out){
    extern __shared__ char sm[];
    char* B1  = sm;                // 16KB: attn half-image, later H-chunk / y images (64 rows)
    char* X3  = sm + OFF_X3;       // 16KB: x3 image (64 rows)
    char* WB0 = sm + OFF_WB0;      // 32KB weight buffer 0 (WO, W2 slabs)
    char* WB1 = sm + OFF_WB1;      // 40KB weight buffer 1 (W1 slabs, Wun)
    __shared__ int ps[64];
    __shared__ float sb1[128];
    __shared__ float sb2[128];
    __shared__ float sbc[NPAD];

    uint32_t b1A = smem_u32(B1), x3A = smem_u32(X3), w0A = smem_u32(WB0), w1A = smem_u32(WB1);

    int tid = threadIdx.x, wid = tid>>5, lane = tid&31;
    int blk = blockIdx.x;          // 0..1023, 64 rows each
    int R0  = blk*64;
    int lr = lane >> 2, lq = lane & 3;
    // 2M x 4N mapping for the N=128 stages
    int wm2 = wid & 1, wn4 = wid >> 1;
    int rb2 = wm2*32, cb4 = wn4*32;
    // 4M x 2N mapping for the logits stage (N=160)
    int wmL = wid & 3, wnL = wid >> 2;
    int rbL = wmL*16, cbL = wnL*80;

    // g0: attn half-image -> B1, WO -> WB0
    {
        const uint4* sA = g_AttnImg + (size_t)(blk>>1)*2048 + (size_t)(blk&1)*1024;
        for (int i=tid;i<1024;i+=256) cpa16(b1A + i*16u, sA + i);
        for (int i=tid;i<2048;i+=256) cpa16(w0A + i*16u, g_WOimg + i);
        CP_COMMIT();
    }
    // g1: W1_0 -> WB1
    for (int i=tid;i<2048;i+=256) cpa16(w1A + i*16u, g_W1img + i);
    CP_COMMIT();

    if (tid < 64) ps[tid] = pv[R0+tid];
    if (tid < 128) sb2[tid] = b2[tid];
    if (tid < NPAD) sbc[tid] = g_biasC[tid];
    CP_WAIT1();            // g0 done
    __syncthreads();

    // ---- stage A: P = attn @ WO ----
    float accA[2][4][4];
    #pragma unroll
    for (int mt=0;mt<2;mt++){
        #pragma unroll
        for (int nt=0;nt<4;nt++){
            #pragma unroll
            for (int q=0;q<4;q++) accA[mt][nt][q]=0.f;
        }
    }
    mma_pass2<4>(accA, b1A, w0A, rb2, cb4, lane);
    __syncthreads();       // WB0 free, B1 free

    // g2: W2_0 -> WB0
    for (int i=tid;i<2048;i+=256) cpa16(w0A + i*16u, g_W2img + i);
    CP_COMMIT();

    // ---- x3 = P + X3F[p]; write x3 image (overlaps g2) ----
    #pragma unroll
    for (int mt=0;mt<2;mt++){
        int r = rb2 + mt*16 + lr;
        int p0 = ps[r], p1 = ps[r+8];
        #pragma unroll
        for (int nt=0;nt<4;nt++){
            int col = cb4 + nt*8 + lq*2;
            wpair(X3, r,   col, accA[mt][nt][0] + g_X3F[p0*D+col], accA[mt][nt][1] + g_X3F[p0*D+col+1]);
            wpair(X3, r+8, col, accA[mt][nt][2] + g_X3F[p1*D+col], accA[mt][nt][3] + g_X3F[p1*D+col+1]);
        }
    }
    CP_WAIT1();            // g1 (W1_0) done
    __syncthreads();

    // ---- mlp accumulator (H@W2 summed over chunks) ----
    float accM[2][4][4];
    #pragma unroll
    for (int mt=0;mt<2;mt++){
        #pragma unroll
        for (int nt=0;nt<4;nt++){
            #pragma unroll
            for (int q=0;q<4;q++) accM[mt][nt][q]=0.f;
        }
    }

    for (int ch=0; ch<4; ch++){
        if (tid < 128) sb1[tid] = bias1[ch*128+tid];

        float accH[2][4][4];
        #pragma unroll
        for (int mt=0;mt<2;mt++){
            #pragma unroll
            for (int nt=0;nt<4;nt++){
                #pragma unroll
                for (int q=0;q<4;q++) accH[mt][nt][q]=0.f;
            }
        }
        mma_pass2<4>(accH, x3A, w1A, rb2, cb4, lane);
        __syncthreads();   // WB1 free; sb1 visible

        // prefetch into WB1: W1_{ch+1} or Wun
        if (ch < 3){
            for (int i=tid;i<2048;i+=256) cpa16(w1A + i*16u, g_W1img + (size_t)(ch+1)*2048 + i);
        } else {
            for (int i=tid;i<2560;i+=256) cpa16(w1A + i*16u, g_WUimg + i);
        }
        CP_COMMIT();

        // H epilogue -> B1 image (overlaps prefetch)
        #pragma unroll
        for (int mt=0;mt<2;mt++){
            int r = rb2 + mt*16 + lr;
            #pragma unroll
            for (int nt=0;nt<4;nt++){
                int col = cb4 + nt*8 + lq*2;
                float b0 = sb1[col], b1v = sb1[col+1];
                wpair(B1, r,   col, fmaxf(accH[mt][nt][0]+b0,0.f), fmaxf(accH[mt][nt][1]+b1v,0.f));
                wpair(B1, r+8, col, fmaxf(accH[mt][nt][2]+b0,0.f), fmaxf(accH[mt][nt][3]+b1v,0.f));
            }
        }
        CP_WAIT1();        // W2_ch done (in WB0)
        __syncthreads();

        mma_pass2<4>(accM, b1A, w0A, rb2, cb4, lane);   // accM += H_ch @ W2_ch
        __syncthreads();   // WB0 free, B1 free

        if (ch < 3){
            for (int i=tid;i<2048;i+=256) cpa16(w0A + i*16u, g_W2img + (size_t)(ch+1)*2048 + i);
            CP_COMMIT();
        }
    }

    // ---- y = x3 + mlp + b2 -> B1 image ----
    #pragma unroll
    for (int mt=0;mt<2;mt++){
        int r = rb2 + mt*16 + lr;
        #pragma unroll
        for (int nt=0;nt<4;nt++){
            int col = cb4 + nt*8 + lq*2;
            float b0 = sb2[col], b1v = sb2[col+1];
            float2 x0 = rpair(X3, r,   col);
            float2 x1 = rpair(X3, r+8, col);
            wpair(B1, r,   col, x0.x + accM[mt][nt][0] + b0, x0.y + accM[mt][nt][1] + b1v);
            wpair(B1, r+8, col, x1.x + accM[mt][nt][2] + b0, x1.y + accM[mt][nt][3] + b1v);
        }
    }
    CP_WAIT0();            // Wun done (in WB1)
    __syncthreads();

    // ---- logits = y @ Wun  (4M x 2N mapping, NT=10) ----
    float accL[10][4];
    #pragma unroll
    for (int nt=0;nt<10;nt++){
        #pragma unroll
        for (int q=0;q<4;q++) accL[nt][q]=0.f;
    }
    mma_pass1<10>(accL, b1A, w1A, rbL, cbL, lane);

    // ---- logits epilogue ----
    {
        int row = R0 + rbL + lr;
        #pragma unroll
        for (int nt=0;nt<10;nt++){
            int col = cbL + nt*8 + lq*2;
            if (col < NOUT){
                out[row*NOUT+col]       = accL[nt][0] + sbc[col];
                out[(row+8)*NOUT+col]   = accL[nt][2] + sbc[col];
            }
            if (col+1 < NOUT){
                out[row*NOUT+col+1]     = accL[nt][1] + sbc[col+1];
                out[(row+8)*NOUT+col+1] = accL[nt][3] + sbc[col+1];
            }
        }
    }
}

// ---------------- launch ----------------
extern "C" void kernel_launch(void* const* d_in, const int* in_sizes, int n_in,
                              void* d_out, int out_size){
    const int*   pv    = (const int*)  d_in[0];
    const int*   av    = (const int*)  d_in[1];
    const int*   bvv   = (const int*)  d_in[2];
    const float* emb   = (const float*)d_in[3];
    const float* pos   = (const float*)d_in[4];
    const float* W_mem = (const float*)d_in[5];
    const float* b_mem = (const float*)d_in[6];
    const float* W_sur = (const float*)d_in[7];
    const float* b_sur = (const float*)d_in[8];
    const float* W_m2r = (const float*)d_in[9];
    const float* b_m2r = (const float*)d_in[10];
    const float* W_Q   = (const float*)d_in[11];
    const float* W_K   = (const float*)d_in[12];
    const float* W_V   = (const float*)d_in[13];
    const float* W_O   = (const float*)d_in[14];
    const float* W1    = (const float*)d_in[15];
    const float* bias1 = (const float*)d_in[16];
    const float* W2    = (const float*)d_in[17];
    const float* b2    = (const float*)d_in[18];
    const float* W_un  = (const float*)d_in[19];
    const float* b_un  = (const float*)d_in[20];
    float* out = (float*)d_out;

    k_prep<<<1312+NP,128>>>(W_O,W1,W2,W_un,b_un,
                            emb,pos,W_mem,b_mem,W_sur,b_sur,W_m2r,b_m2r,W_Q,W_K,W_V);
    k_ttab<<<NP,128>>>();
    k_attn<<<BB/8,256>>>(pv,av,bvv);

    cudaFuncSetAttribute(k_fused, cudaFuncAttributeMaxDynamicSharedMemorySize, FU_SMEM);
    k_fused<<<BB/64,256,FU_SMEM>>>(pv,bias1,b2,out);
}